// round 14
// baseline (speedup 1.0000x reference)
#include <cuda_runtime.h>
#include <cuda_fp16.h>
#include <cstdint>
#include <math_constants.h>

#define MAXN 100000
#define MAXE 500000
#define IN_DIM 128
#define HID 512
#define NCLS 40
#define SCAN_BLK 512
#define NSCANB ((MAXN + SCAN_BLK - 1) / SCAN_BLK)   // 196

__device__ int      g_degi  [MAXN];      // zero at entry; scan_a restores zeros
__device__ float    g_dinv  [MAXN];
__device__ int      g_rowptr[MAXN + 1];
__device__ int      g_rank  [MAXE];      // within-row rank of each edge
__device__ int      g_bsum  [256];
__device__ int      g_csrc  [MAXE];
__device__ uint32_t g_axp   [(size_t)MAXN * 64];    // bf16x2-packed agg(x) [row][kk]
__device__ uint32_t g_w1p   [HID * 64];             // W1 packed n-major [n][kk]
__device__ uint32_t g_w2p   [NCLS * 256];            // W2 packed n-major [n][kk]
__device__ uint32_t g_g2h   [(size_t)MAXN * 20];    // fp16x2-packed g2 [row][cc]

// ---------------------------------------------------------------------------
__device__ __forceinline__ uint32_t packbf(float a, float b) {
    uint32_t o;
    asm("cvt.rn.bf16x2.f32 %0, %2, %1;" : "=r"(o) : "f"(a), "f"(b));
    return o;
}
__device__ __forceinline__ uint32_t packhf(float a, float b) {
    uint32_t o;
    asm("cvt.rn.f16x2.f32 %0, %2, %1;" : "=r"(o) : "f"(a), "f"(b));
    return o;
}

// ---------------------------------------------------------------------------
// degree histogram (returning per-edge rank) + weight packing, one launch
__global__ void k_degw(const int* __restrict__ dst, const float* __restrict__ W1,
                       const float* __restrict__ W2, int E) {
    int i = blockIdx.x * blockDim.x + threadIdx.x;
    if (i < E) g_rank[i] = atomicAdd(&g_degi[dst[i]], 1);
    if (i < HID * 64) {
        int kk = i >> 9;
        int n  = i & 511;
        g_w1p[n * 64 + kk] =
            packbf(W1[(size_t)(2 * kk) * HID + n], W1[(size_t)(2 * kk + 1) * HID + n]);
    } else if (i < HID * 64 + NCLS * 256) {
        int f  = i - HID * 64;
        int kk = f / NCLS;
        int n  = f % NCLS;
        g_w2p[n * 256 + kk] =
            packbf(W2[(size_t)(2 * kk) * NCLS + n], W2[(size_t)(2 * kk + 1) * NCLS + n]);
    }
}

// scan phase A: per-block scan of degi + dinv; restores degi to 0 for next replay
__global__ void k_scan_a(int N) {
    __shared__ int s[256];
    int t = threadIdx.x;
    int base = blockIdx.x * SCAN_BLK;
    int i0 = base + 2 * t, i1 = i0 + 1;
    int c0 = 0, c1 = 0;
    if (i0 < N) { c0 = g_degi[i0]; g_degi[i0] = 0; g_dinv[i0] = rsqrtf((float)(c0 + 1)); }
    if (i1 < N) { c1 = g_degi[i1]; g_degi[i1] = 0; g_dinv[i1] = rsqrtf((float)(c1 + 1)); }
    int sum = c0 + c1;
    s[t] = sum;
    __syncthreads();
    #pragma unroll
    for (int off = 1; off < 256; off <<= 1) {
        int v = (t >= off) ? s[t - off] : 0;
        __syncthreads();
        s[t] += v;
        __syncthreads();
    }
    int ex = s[t] - sum;
    if (i0 < N) g_rowptr[i0] = ex;
    if (i1 < N) g_rowptr[i1] = ex + c0;
    if (t == 255) g_bsum[blockIdx.x] = s[255];
}

// scan phase C with in-kernel bsum prefix
__global__ void k_scan_c(int N, int E, int NB) {
    __shared__ int sc[256];
    __shared__ int ex[256];
    int t = threadIdx.x;
    int v0 = (t < NB) ? g_bsum[t] : 0;
    sc[t] = v0;
    __syncthreads();
    #pragma unroll
    for (int off = 1; off < 256; off <<= 1) {
        int v = (t >= off) ? sc[t - off] : 0;
        __syncthreads();
        sc[t] += v;
        __syncthreads();
    }
    ex[t] = sc[t] - v0;
    __syncthreads();
    int i = blockIdx.x * blockDim.x + t;
    if (i < N) g_rowptr[i] += ex[i / SCAN_BLK];
    if (i == 0) g_rowptr[N] = E;
}

// atomic-free scatter: position = rowptr[dst] + rank
__global__ void k_scatter(const int* __restrict__ src, const int* __restrict__ dst,
                          int E) {
    int e = blockIdx.x * blockDim.x + threadIdx.x;
    if (e >= E) return;
    g_csrc[g_rowptr[dst[e]] + g_rank[e]] = src[e];
}

// ---------------------------------------------------------------------------
// g_axp[i] = bf16x2( dinv[i]*sum dinv[s]x[s] + dinv[i]^2 x[i] ), packed k-pairs
__global__ void k_gax(const float* __restrict__ x, int N) {
    int i = (int)((blockIdx.x * (unsigned)blockDim.x + threadIdx.x) >> 5);
    int l = threadIdx.x & 31;
    if (i >= N) return;
    int b  = g_rowptr[i];
    int e2 = g_rowptr[i + 1];
    float4 acc = make_float4(0.f, 0.f, 0.f, 0.f);
    int j = b;
    for (; j + 4 <= e2; j += 4) {
        int s0 = g_csrc[j], s1 = g_csrc[j + 1], s2 = g_csrc[j + 2], s3 = g_csrc[j + 3];
        float w0 = g_dinv[s0], w1 = g_dinv[s1], w2 = g_dinv[s2], w3 = g_dinv[s3];
        float4 v0 = *(const float4*)(x + (size_t)s0 * IN_DIM + l * 4);
        float4 v1 = *(const float4*)(x + (size_t)s1 * IN_DIM + l * 4);
        float4 v2 = *(const float4*)(x + (size_t)s2 * IN_DIM + l * 4);
        float4 v3 = *(const float4*)(x + (size_t)s3 * IN_DIM + l * 4);
        acc.x += w0 * v0.x + w1 * v1.x + w2 * v2.x + w3 * v3.x;
        acc.y += w0 * v0.y + w1 * v1.y + w2 * v2.y + w3 * v3.y;
        acc.z += w0 * v0.z + w1 * v1.z + w2 * v2.z + w3 * v3.z;
        acc.w += w0 * v0.w + w1 * v1.w + w2 * v2.w + w3 * v3.w;
    }
    for (; j < e2; j++) {
        int s = g_csrc[j];
        float w = g_dinv[s];
        float4 v = *(const float4*)(x + (size_t)s * IN_DIM + l * 4);
        acc.x += w * v.x; acc.y += w * v.y; acc.z += w * v.z; acc.w += w * v.w;
    }
    float di = g_dinv[i];
    float d2 = di * di;
    float4 xi = *(const float4*)(x + (size_t)i * IN_DIM + l * 4);
    uint2 o2;
    o2.x = packbf(di * acc.x + d2 * xi.x, di * acc.y + d2 * xi.y);
    o2.y = packbf(di * acc.z + d2 * xi.z, di * acc.w + d2 * xi.w);
    *(uint2*)(g_axp + (size_t)i * 64 + l * 2) = o2;
}

// ---------------------------------------------------------------------------
// Fused tensor-core kernel: g2 = relu(Ax @ W1 + b1) @ W2 (bf16 mma, ldmatrix)
// g2 written as fp16x2 pairs.
#define AS_S 68   // row stride (u32); (r*68)%32 = 4r -> conflict-free ldmatrix
__global__ void __launch_bounds__(256, 2)
k_fused(const float* __restrict__ b1, int N) {
    extern __shared__ uint32_t sm[];
    uint32_t* As  = sm;                 // [128][68]  A tile (bf16 pairs)
    uint32_t* Bn  = As + 128 * AS_S;    // [128][68]  W1 chunk n-major; later Ps
    uint32_t* W2n = Bn + 128 * AS_S;    // [40][68]   W2 chunk n-major

    const int t    = threadIdx.x;
    const int wid  = t >> 5;
    const int lane = t & 31;
    const int tg   = lane & 3;
    const int wm   = wid & 3;
    const int wn   = wid >> 2;
    const int row0 = blockIdx.x * 128;

    const int lrow = lane & 15;
    const int lcol = (lane >> 4) << 2;

    const uint32_t As_sa = (uint32_t)__cvta_generic_to_shared(As);
    const uint32_t Bn_sa = (uint32_t)__cvta_generic_to_shared(Bn);
    const uint32_t W2_sa = (uint32_t)__cvta_generic_to_shared(W2n);

    #pragma unroll
    for (int i = 0; i < 8; i++) {
        int f  = t + i * 256;
        int r  = f >> 4;
        int c4 = f & 15;
        uint4 v = make_uint4(0u, 0u, 0u, 0u);
        int gr = row0 + r;
        if (gr < N) v = *(const uint4*)(g_axp + (size_t)gr * 64 + c4 * 4);
        *(uint4*)&As[r * AS_S + c4 * 4] = v;
    }

    float acc2[5][4];
    #pragma unroll
    for (int a = 0; a < 5; a++)
        #pragma unroll
        for (int b = 0; b < 4; b++) acc2[a][b] = 0.f;

    for (int nc = 0; nc < 4; nc++) {
        #pragma unroll
        for (int i = 0; i < 8; i++) {
            int f  = t + i * 256;
            int r  = f >> 4;
            int c4 = f & 15;
            uint4 v = *(const uint4*)(g_w1p + (size_t)(nc * 128 + r) * 64 + c4 * 4);
            *(uint4*)&Bn[r * AS_S + c4 * 4] = v;
        }
        #pragma unroll
        for (int i = 0; i < 3; i++) {
            int f = t + i * 256;
            if (f < 640) {
                int r  = f >> 4;
                int c4 = f & 15;
                uint4 v = *(const uint4*)(g_w2p + (size_t)r * 256 + nc * 64 + c4 * 4);
                *(uint4*)&W2n[r * AS_S + c4 * 4] = v;
            }
        }
        __syncthreads();

        float acc1[2][8][4];
        #pragma unroll
        for (int a = 0; a < 2; a++)
            #pragma unroll
            for (int b = 0; b < 8; b++)
                #pragma unroll
                for (int c = 0; c < 4; c++) acc1[a][b][c] = 0.f;

        #pragma unroll
        for (int ks = 0; ks < 8; ks++) {
            const int kk0 = ks * 8;
            uint32_t af[2][4];
            #pragma unroll
            for (int mi = 0; mi < 2; mi++) {
                uint32_t addr = As_sa +
                    4u * ((wm * 32 + mi * 16 + lrow) * AS_S + kk0 + lcol);
                asm volatile(
                    "ldmatrix.sync.aligned.m8n8.x4.shared.b16 {%0,%1,%2,%3}, [%4];"
                    : "=r"(af[mi][0]), "=r"(af[mi][1]), "=r"(af[mi][2]), "=r"(af[mi][3])
                    : "r"(addr));
            }
            uint32_t bf[8][2];
            #pragma unroll
            for (int np = 0; np < 4; np++) {
                uint32_t addr = Bn_sa +
                    4u * ((wn * 64 + np * 16 + lrow) * AS_S + kk0 + lcol);
                asm volatile(
                    "ldmatrix.sync.aligned.m8n8.x4.shared.b16 {%0,%1,%2,%3}, [%4];"
                    : "=r"(bf[np * 2][0]), "=r"(bf[np * 2 + 1][0]),
                      "=r"(bf[np * 2][1]), "=r"(bf[np * 2 + 1][1])
                    : "r"(addr));
            }
            #pragma unroll
            for (int mi = 0; mi < 2; mi++)
                #pragma unroll
                for (int ni = 0; ni < 8; ni++) {
                    float* d = acc1[mi][ni];
                    asm volatile(
                        "mma.sync.aligned.m16n8k16.row.col.f32.bf16.bf16.f32 "
                        "{%0,%1,%2,%3}, {%4,%5,%6,%7}, {%8,%9}, {%0,%1,%2,%3};"
                        : "+f"(d[0]), "+f"(d[1]), "+f"(d[2]), "+f"(d[3])
                        : "r"(af[mi][0]), "r"(af[mi][1]), "r"(af[mi][2]), "r"(af[mi][3]),
                          "r"(bf[ni][0]), "r"(bf[ni][1]));
                }
        }
        __syncthreads();

        const int g = lane >> 2;
        #pragma unroll
        for (int ni = 0; ni < 8; ni++) {
            int lc = wn * 64 + ni * 8 + tg * 2;
            int kk = lc >> 1;
            float2 bias = *(const float2*)(b1 + nc * 128 + lc);
            #pragma unroll
            for (int mi = 0; mi < 2; mi++) {
                int lr = wm * 32 + mi * 16 + g;
                float* d = acc1[mi][ni];
                Bn[lr * AS_S + kk] =
                    packbf(fmaxf(d[0] + bias.x, 0.f), fmaxf(d[1] + bias.y, 0.f));
                Bn[(lr + 8) * AS_S + kk] =
                    packbf(fmaxf(d[2] + bias.x, 0.f), fmaxf(d[3] + bias.y, 0.f));
            }
        }
        __syncthreads();

        #pragma unroll
        for (int ks = 0; ks < 8; ks++) {
            const int kk0 = ks * 8;
            uint32_t af[4];
            {
                uint32_t addr = Bn_sa +
                    4u * ((wid * 16 + lrow) * AS_S + kk0 + lcol);
                asm volatile(
                    "ldmatrix.sync.aligned.m8n8.x4.shared.b16 {%0,%1,%2,%3}, [%4];"
                    : "=r"(af[0]), "=r"(af[1]), "=r"(af[2]), "=r"(af[3])
                    : "r"(addr));
            }
            uint32_t bf2[5][2];
            #pragma unroll
            for (int np = 0; np < 2; np++) {
                uint32_t addr = W2_sa +
                    4u * ((np * 16 + lrow) * AS_S + kk0 + lcol);
                asm volatile(
                    "ldmatrix.sync.aligned.m8n8.x4.shared.b16 {%0,%1,%2,%3}, [%4];"
                    : "=r"(bf2[np * 2][0]), "=r"(bf2[np * 2 + 1][0]),
                      "=r"(bf2[np * 2][1]), "=r"(bf2[np * 2 + 1][1])
                    : "r"(addr));
            }
            {
                uint32_t addr = W2_sa +
                    4u * ((32 + (lane & 7)) * AS_S + kk0 + (((lane >> 3) & 1) << 2));
                asm volatile(
                    "ldmatrix.sync.aligned.m8n8.x2.shared.b16 {%0,%1}, [%2];"
                    : "=r"(bf2[4][0]), "=r"(bf2[4][1])
                    : "r"(addr));
            }
            #pragma unroll
            for (int ni = 0; ni < 5; ni++) {
                float* d = acc2[ni];
                asm volatile(
                    "mma.sync.aligned.m16n8k16.row.col.f32.bf16.bf16.f32 "
                    "{%0,%1,%2,%3}, {%4,%5,%6,%7}, {%8,%9}, {%0,%1,%2,%3};"
                    : "+f"(d[0]), "+f"(d[1]), "+f"(d[2]), "+f"(d[3])
                    : "r"(af[0]), "r"(af[1]), "r"(af[2]), "r"(af[3]),
                      "r"(bf2[ni][0]), "r"(bf2[ni][1]));
            }
        }
        __syncthreads();
    }

    // ---- epilogue: write g2 as fp16x2 pairs (col pair cc = ni*4+tg) ----
    const int g = lane >> 2;
    const int m0 = row0 + wid * 16;
    #pragma unroll
    for (int ni = 0; ni < 5; ni++) {
        int cc = ni * 4 + tg;
        float* d = acc2[ni];
        int r0 = m0 + g;
        if (r0 < N) g_g2h[(size_t)r0 * 20 + cc] = packhf(d[0], d[1]);
        int r1 = r0 + 8;
        if (r1 < N) g_g2h[(size_t)r1 * 20 + cc] = packhf(d[2], d[3]);
    }
}

// ---------------------------------------------------------------------------
// CSR-gather aggregation of fp16 g2 + bias + log_softmax -> out.
// One warp per node; lane l<20 covers cols 2l, 2l+1.
__global__ void k_gout(const float* __restrict__ b2, float* __restrict__ out, int N) {
    int i = (int)((blockIdx.x * (unsigned)blockDim.x + threadIdx.x) >> 5);
    int l = threadIdx.x & 31;
    if (i >= N) return;
    float v0 = -CUDART_INF_F, v1 = -CUDART_INF_F;
    if (l < 20) {
        int b  = g_rowptr[i];
        int e2 = g_rowptr[i + 1];
        float a0 = 0.f, a1 = 0.f;
        int j = b;
        for (; j + 4 <= e2; j += 4) {
            int s0 = g_csrc[j],     s1 = g_csrc[j + 1];
            int s2 = g_csrc[j + 2], s3 = g_csrc[j + 3];
            float w0 = g_dinv[s0], w1 = g_dinv[s1], w2 = g_dinv[s2], w3 = g_dinv[s3];
            float2 f0 = __half22float2(*(const __half2*)(g_g2h + (size_t)s0 * 20 + l));
            float2 f1 = __half22float2(*(const __half2*)(g_g2h + (size_t)s1 * 20 + l));
            float2 f2 = __half22float2(*(const __half2*)(g_g2h + (size_t)s2 * 20 + l));
            float2 f3 = __half22float2(*(const __half2*)(g_g2h + (size_t)s3 * 20 + l));
            a0 += w0 * f0.x + w1 * f1.x + w2 * f2.x + w3 * f3.x;
            a1 += w0 * f0.y + w1 * f1.y + w2 * f2.y + w3 * f3.y;
        }
        for (; j < e2; j++) {
            int s = g_csrc[j];
            float w = g_dinv[s];
            float2 f = __half22float2(*(const __half2*)(g_g2h + (size_t)s * 20 + l));
            a0 += w * f.x;
            a1 += w * f.y;
        }
        float di = g_dinv[i];
        float d2 = di * di;
        float2 fs = __half22float2(*(const __half2*)(g_g2h + (size_t)i * 20 + l));
        float2 bias = *(const float2*)(b2 + 2 * l);
        v0 = di * a0 + d2 * fs.x + bias.x;
        v1 = di * a1 + d2 * fs.y + bias.y;
    }
    float m = fmaxf(v0, v1);
    #pragma unroll
    for (int o = 16; o; o >>= 1) m = fmaxf(m, __shfl_xor_sync(0xffffffffu, m, o));
    float s = (l < 20) ? (expf(v0 - m) + expf(v1 - m)) : 0.f;
    #pragma unroll
    for (int o = 16; o; o >>= 1) s += __shfl_xor_sync(0xffffffffu, s, o);
    float lse = m + logf(s);
    if (l < 20)
        *(float2*)(out + (size_t)i * NCLS + 2 * l) = make_float2(v0 - lse, v1 - lse);
}

// ---------------------------------------------------------------------------
extern "C" void kernel_launch(void* const* d_in, const int* in_sizes, int n_in,
                              void* d_out, int out_size) {
    const float* x  = (const float*)d_in[0];
    const int*   ei = (const int*)  d_in[1];
    const float* W1 = (const float*)d_in[2];
    const float* b1 = (const float*)d_in[3];
    const float* W2 = (const float*)d_in[4];
    const float* b2 = (const float*)d_in[5];
    float* out = (float*)d_out;

    int N = in_sizes[0] / IN_DIM;
    int E = in_sizes[1] / 2;
    const int* src = ei;
    const int* dst = ei + E;

    static int smem_set = 0;
    const int SMEM_FUSED = (128 * AS_S * 2 + 40 * AS_S) * 4;   // 80,512 B
    if (!smem_set) {
        cudaFuncSetAttribute(k_fused, cudaFuncAttributeMaxDynamicSharedMemorySize,
                             SMEM_FUSED);
        smem_set = 1;
    }

    int NB = (N + SCAN_BLK - 1) / SCAN_BLK;   // 196

    // 7 launches; g_degi is zero on entry (BSS init + scan_a restore)
    k_degw<<<(E + 255) / 256, 256>>>(dst, W1, W2, E);
    k_scan_a<<<NB, 256>>>(N);
    k_scan_c<<<(N + 255) / 256, 256>>>(N, E, NB);
    k_scatter<<<(E + 255) / 256, 256>>>(src, dst, E);

    {
        long threads = (long)N * 32;
        k_gax<<<(int)((threads + 255) / 256), 256>>>(x, N);
    }

    k_fused<<<(N + 127) / 128, 256, SMEM_FUSED>>>(b1, N);

    {
        long threads = (long)N * 32;
        k_gout<<<(int)((threads + 255) / 256), 256>>>(b2, out, N);
    }
}

// round 15
// speedup vs baseline: 1.4369x; 1.4369x over previous
#include <cuda_runtime.h>
#include <cuda_fp16.h>
#include <cstdint>
#include <math_constants.h>

#define MAXN 100000
#define MAXE 500000
#define IN_DIM 128
#define HID 512
#define NCLS 40
#define SCAN_BLK 512
#define NSCANB ((MAXN + SCAN_BLK - 1) / SCAN_BLK)   // 196

__device__ int      g_degi  [MAXN];      // zero at entry; scan_a restores zeros
__device__ float    g_dinv  [MAXN];
__device__ int      g_rowptr[MAXN + 1];
__device__ int      g_cursor[MAXN];
__device__ int      g_bsum  [256];
__device__ int      g_csrc  [MAXE];
__device__ uint32_t g_axp   [(size_t)MAXN * 64];    // bf16x2-packed agg(x) [row][kk]
__device__ uint32_t g_w1p   [HID * 64];             // W1 packed n-major [n][kk]
__device__ uint32_t g_w2p   [NCLS * 256];           // W2 packed n-major [n][kk]
__device__ uint32_t g_g2h   [(size_t)MAXN * 20];    // fp16x2-packed g2 [row][cc]

// ---------------------------------------------------------------------------
__device__ __forceinline__ uint32_t packbf(float a, float b) {
    uint32_t o;
    asm("cvt.rn.bf16x2.f32 %0, %2, %1;" : "=r"(o) : "f"(a), "f"(b));
    return o;
}
__device__ __forceinline__ uint32_t packhf(float a, float b) {
    uint32_t o;
    asm("cvt.rn.f16x2.f32 %0, %2, %1;" : "=r"(o) : "f"(a), "f"(b));
    return o;
}

// inclusive warp scan (full warp participates)
__device__ __forceinline__ int wscan(int v) {
    #pragma unroll
    for (int off = 1; off < 32; off <<= 1) {
        int u = __shfl_up_sync(0xffffffffu, v, off);
        if ((threadIdx.x & 31) >= off) v += u;
    }
    return v;
}

// block-level inclusive scan over 256 threads (returns inclusive; 2 barriers)
__device__ __forceinline__ int bscan256(int sum) {
    __shared__ int wtot[8];
    int wid  = threadIdx.x >> 5;
    int lane = threadIdx.x & 31;
    int inc = wscan(sum);
    if (lane == 31) wtot[wid] = inc;
    __syncthreads();
    if (wid == 0) {
        int w = (lane < 8) ? wtot[lane] : 0;
        w = wscan(w);
        if (lane < 8) wtot[lane] = w;
    }
    __syncthreads();
    int base = (wid > 0) ? wtot[wid - 1] : 0;
    return base + inc;
}

// ---------------------------------------------------------------------------
// degree histogram (REDG — result unused!) + weight packing, one launch
__global__ void k_degw(const int* __restrict__ dst, const float* __restrict__ W1,
                       const float* __restrict__ W2, int E) {
    int i = blockIdx.x * blockDim.x + threadIdx.x;
    if (i < E) atomicAdd(&g_degi[dst[i]], 1);
    if (i < HID * 64) {
        int kk = i >> 9;
        int n  = i & 511;
        g_w1p[n * 64 + kk] =
            packbf(W1[(size_t)(2 * kk) * HID + n], W1[(size_t)(2 * kk + 1) * HID + n]);
    } else if (i < HID * 64 + NCLS * 256) {
        int f  = i - HID * 64;
        int kk = f / NCLS;
        int n  = f % NCLS;
        g_w2p[n * 256 + kk] =
            packbf(W2[(size_t)(2 * kk) * NCLS + n], W2[(size_t)(2 * kk + 1) * NCLS + n]);
    }
}

// scan phase A (shuffle scan): per-block scan of degi + dinv; restores degi=0
__global__ void k_scan_a(int N) {
    int t = threadIdx.x;
    int base = blockIdx.x * SCAN_BLK;
    int i0 = base + 2 * t, i1 = i0 + 1;
    int c0 = 0, c1 = 0;
    if (i0 < N) { c0 = g_degi[i0]; g_degi[i0] = 0; g_dinv[i0] = rsqrtf((float)(c0 + 1)); }
    if (i1 < N) { c1 = g_degi[i1]; g_degi[i1] = 0; g_dinv[i1] = rsqrtf((float)(c1 + 1)); }
    int sum = c0 + c1;
    int inc = bscan256(sum);
    int ex = inc - sum;
    if (i0 < N) g_rowptr[i0] = ex;
    if (i1 < N) g_rowptr[i1] = ex + c0;
    if (t == 255) g_bsum[blockIdx.x] = inc;
}

// scan phase C (shuffle scan of bsum) + rowptr finalize + cursor init
__global__ void k_scan_c(int N, int E, int NB) {
    __shared__ int ex[256];
    int t = threadIdx.x;
    int v0 = (t < NB) ? g_bsum[t] : 0;
    int inc = bscan256(v0);
    ex[t] = inc - v0;
    __syncthreads();
    int i = blockIdx.x * blockDim.x + t;
    if (i < N) {
        int v = g_rowptr[i] + ex[i / SCAN_BLK];
        g_rowptr[i] = v;
        g_cursor[i] = v;
    }
    if (i == 0) g_rowptr[N] = E;
}

__global__ void k_scatter(const int* __restrict__ src, const int* __restrict__ dst,
                          int E) {
    int e = blockIdx.x * blockDim.x + threadIdx.x;
    if (e >= E) return;
    int pos = atomicAdd(&g_cursor[dst[e]], 1);
    g_csrc[pos] = src[e];
}

// ---------------------------------------------------------------------------
// g_axp[i] = bf16x2( dinv[i]*sum dinv[s]x[s] + dinv[i]^2 x[i] ), packed k-pairs
__global__ void k_gax(const float* __restrict__ x, int N) {
    int i = (int)((blockIdx.x * (unsigned)blockDim.x + threadIdx.x) >> 5);
    int l = threadIdx.x & 31;
    if (i >= N) return;
    int b  = g_rowptr[i];
    int e2 = g_rowptr[i + 1];
    float4 acc = make_float4(0.f, 0.f, 0.f, 0.f);
    int j = b;
    for (; j + 4 <= e2; j += 4) {
        int s0 = g_csrc[j], s1 = g_csrc[j + 1], s2 = g_csrc[j + 2], s3 = g_csrc[j + 3];
        float w0 = g_dinv[s0], w1 = g_dinv[s1], w2 = g_dinv[s2], w3 = g_dinv[s3];
        float4 v0 = *(const float4*)(x + (size_t)s0 * IN_DIM + l * 4);
        float4 v1 = *(const float4*)(x + (size_t)s1 * IN_DIM + l * 4);
        float4 v2 = *(const float4*)(x + (size_t)s2 * IN_DIM + l * 4);
        float4 v3 = *(const float4*)(x + (size_t)s3 * IN_DIM + l * 4);
        acc.x += w0 * v0.x + w1 * v1.x + w2 * v2.x + w3 * v3.x;
        acc.y += w0 * v0.y + w1 * v1.y + w2 * v2.y + w3 * v3.y;
        acc.z += w0 * v0.z + w1 * v1.z + w2 * v2.z + w3 * v3.z;
        acc.w += w0 * v0.w + w1 * v1.w + w2 * v2.w + w3 * v3.w;
    }
    for (; j < e2; j++) {
        int s = g_csrc[j];
        float w = g_dinv[s];
        float4 v = *(const float4*)(x + (size_t)s * IN_DIM + l * 4);
        acc.x += w * v.x; acc.y += w * v.y; acc.z += w * v.z; acc.w += w * v.w;
    }
    float di = g_dinv[i];
    float d2 = di * di;
    float4 xi = *(const float4*)(x + (size_t)i * IN_DIM + l * 4);
    uint2 o2;
    o2.x = packbf(di * acc.x + d2 * xi.x, di * acc.y + d2 * xi.y);
    o2.y = packbf(di * acc.z + d2 * xi.z, di * acc.w + d2 * xi.w);
    *(uint2*)(g_axp + (size_t)i * 64 + l * 2) = o2;
}

// ---------------------------------------------------------------------------
// Fused tensor-core kernel: g2 = relu(Ax @ W1 + b1) @ W2 (bf16 mma, ldmatrix)
// g2 written as fp16x2 pairs.
#define AS_S 68   // row stride (u32); (r*68)%32 = 4r -> conflict-free ldmatrix
__global__ void __launch_bounds__(256, 2)
k_fused(const float* __restrict__ b1, int N) {
    extern __shared__ uint32_t sm[];
    uint32_t* As  = sm;                 // [128][68]  A tile (bf16 pairs)
    uint32_t* Bn  = As + 128 * AS_S;    // [128][68]  W1 chunk n-major; later Ps
    uint32_t* W2n = Bn + 128 * AS_S;    // [40][68]   W2 chunk n-major

    const int t    = threadIdx.x;
    const int wid  = t >> 5;
    const int lane = t & 31;
    const int tg   = lane & 3;
    const int wm   = wid & 3;
    const int wn   = wid >> 2;
    const int row0 = blockIdx.x * 128;

    const int lrow = lane & 15;
    const int lcol = (lane >> 4) << 2;

    const uint32_t As_sa = (uint32_t)__cvta_generic_to_shared(As);
    const uint32_t Bn_sa = (uint32_t)__cvta_generic_to_shared(Bn);
    const uint32_t W2_sa = (uint32_t)__cvta_generic_to_shared(W2n);

    #pragma unroll
    for (int i = 0; i < 8; i++) {
        int f  = t + i * 256;
        int r  = f >> 4;
        int c4 = f & 15;
        uint4 v = make_uint4(0u, 0u, 0u, 0u);
        int gr = row0 + r;
        if (gr < N) v = *(const uint4*)(g_axp + (size_t)gr * 64 + c4 * 4);
        *(uint4*)&As[r * AS_S + c4 * 4] = v;
    }

    float acc2[5][4];
    #pragma unroll
    for (int a = 0; a < 5; a++)
        #pragma unroll
        for (int b = 0; b < 4; b++) acc2[a][b] = 0.f;

    for (int nc = 0; nc < 4; nc++) {
        #pragma unroll
        for (int i = 0; i < 8; i++) {
            int f  = t + i * 256;
            int r  = f >> 4;
            int c4 = f & 15;
            uint4 v = *(const uint4*)(g_w1p + (size_t)(nc * 128 + r) * 64 + c4 * 4);
            *(uint4*)&Bn[r * AS_S + c4 * 4] = v;
        }
        #pragma unroll
        for (int i = 0; i < 3; i++) {
            int f = t + i * 256;
            if (f < 640) {
                int r  = f >> 4;
                int c4 = f & 15;
                uint4 v = *(const uint4*)(g_w2p + (size_t)r * 256 + nc * 64 + c4 * 4);
                *(uint4*)&W2n[r * AS_S + c4 * 4] = v;
            }
        }
        __syncthreads();

        float acc1[2][8][4];
        #pragma unroll
        for (int a = 0; a < 2; a++)
            #pragma unroll
            for (int b = 0; b < 8; b++)
                #pragma unroll
                for (int c = 0; c < 4; c++) acc1[a][b][c] = 0.f;

        #pragma unroll
        for (int ks = 0; ks < 8; ks++) {
            const int kk0 = ks * 8;
            uint32_t af[2][4];
            #pragma unroll
            for (int mi = 0; mi < 2; mi++) {
                uint32_t addr = As_sa +
                    4u * ((wm * 32 + mi * 16 + lrow) * AS_S + kk0 + lcol);
                asm volatile(
                    "ldmatrix.sync.aligned.m8n8.x4.shared.b16 {%0,%1,%2,%3}, [%4];"
                    : "=r"(af[mi][0]), "=r"(af[mi][1]), "=r"(af[mi][2]), "=r"(af[mi][3])
                    : "r"(addr));
            }
            uint32_t bf[8][2];
            #pragma unroll
            for (int np = 0; np < 4; np++) {
                uint32_t addr = Bn_sa +
                    4u * ((wn * 64 + np * 16 + lrow) * AS_S + kk0 + lcol);
                asm volatile(
                    "ldmatrix.sync.aligned.m8n8.x4.shared.b16 {%0,%1,%2,%3}, [%4];"
                    : "=r"(bf[np * 2][0]), "=r"(bf[np * 2 + 1][0]),
                      "=r"(bf[np * 2][1]), "=r"(bf[np * 2 + 1][1])
                    : "r"(addr));
            }
            #pragma unroll
            for (int mi = 0; mi < 2; mi++)
                #pragma unroll
                for (int ni = 0; ni < 8; ni++) {
                    float* d = acc1[mi][ni];
                    asm volatile(
                        "mma.sync.aligned.m16n8k16.row.col.f32.bf16.bf16.f32 "
                        "{%0,%1,%2,%3}, {%4,%5,%6,%7}, {%8,%9}, {%0,%1,%2,%3};"
                        : "+f"(d[0]), "+f"(d[1]), "+f"(d[2]), "+f"(d[3])
                        : "r"(af[mi][0]), "r"(af[mi][1]), "r"(af[mi][2]), "r"(af[mi][3]),
                          "r"(bf[ni][0]), "r"(bf[ni][1]));
                }
        }
        __syncthreads();

        const int g = lane >> 2;
        #pragma unroll
        for (int ni = 0; ni < 8; ni++) {
            int lc = wn * 64 + ni * 8 + tg * 2;
            int kk = lc >> 1;
            float2 bias = *(const float2*)(b1 + nc * 128 + lc);
            #pragma unroll
            for (int mi = 0; mi < 2; mi++) {
                int lr = wm * 32 + mi * 16 + g;
                float* d = acc1[mi][ni];
                Bn[lr * AS_S + kk] =
                    packbf(fmaxf(d[0] + bias.x, 0.f), fmaxf(d[1] + bias.y, 0.f));
                Bn[(lr + 8) * AS_S + kk] =
                    packbf(fmaxf(d[2] + bias.x, 0.f), fmaxf(d[3] + bias.y, 0.f));
            }
        }
        __syncthreads();

        #pragma unroll
        for (int ks = 0; ks < 8; ks++) {
            const int kk0 = ks * 8;
            uint32_t af[4];
            {
                uint32_t addr = Bn_sa +
                    4u * ((wid * 16 + lrow) * AS_S + kk0 + lcol);
                asm volatile(
                    "ldmatrix.sync.aligned.m8n8.x4.shared.b16 {%0,%1,%2,%3}, [%4];"
                    : "=r"(af[0]), "=r"(af[1]), "=r"(af[2]), "=r"(af[3])
                    : "r"(addr));
            }
            uint32_t bf2[5][2];
            #pragma unroll
            for (int np = 0; np < 2; np++) {
                uint32_t addr = W2_sa +
                    4u * ((np * 16 + lrow) * AS_S + kk0 + lcol);
                asm volatile(
                    "ldmatrix.sync.aligned.m8n8.x4.shared.b16 {%0,%1,%2,%3}, [%4];"
                    : "=r"(bf2[np * 2][0]), "=r"(bf2[np * 2 + 1][0]),
                      "=r"(bf2[np * 2][1]), "=r"(bf2[np * 2 + 1][1])
                    : "r"(addr));
            }
            {
                uint32_t addr = W2_sa +
                    4u * ((32 + (lane & 7)) * AS_S + kk0 + (((lane >> 3) & 1) << 2));
                asm volatile(
                    "ldmatrix.sync.aligned.m8n8.x2.shared.b16 {%0,%1}, [%2];"
                    : "=r"(bf2[4][0]), "=r"(bf2[4][1])
                    : "r"(addr));
            }
            #pragma unroll
            for (int ni = 0; ni < 5; ni++) {
                float* d = acc2[ni];
                asm volatile(
                    "mma.sync.aligned.m16n8k16.row.col.f32.bf16.bf16.f32 "
                    "{%0,%1,%2,%3}, {%4,%5,%6,%7}, {%8,%9}, {%0,%1,%2,%3};"
                    : "+f"(d[0]), "+f"(d[1]), "+f"(d[2]), "+f"(d[3])
                    : "r"(af[0]), "r"(af[1]), "r"(af[2]), "r"(af[3]),
                      "r"(bf2[ni][0]), "r"(bf2[ni][1]));
            }
        }
        __syncthreads();
    }

    // ---- epilogue: write g2 as fp16x2 pairs (col pair cc = ni*4+tg) ----
    const int g = lane >> 2;
    const int m0 = row0 + wid * 16;
    #pragma unroll
    for (int ni = 0; ni < 5; ni++) {
        int cc = ni * 4 + tg;
        float* d = acc2[ni];
        int r0 = m0 + g;
        if (r0 < N) g_g2h[(size_t)r0 * 20 + cc] = packhf(d[0], d[1]);
        int r1 = r0 + 8;
        if (r1 < N) g_g2h[(size_t)r1 * 20 + cc] = packhf(d[2], d[3]);
    }
}

// ---------------------------------------------------------------------------
// CSR-gather aggregation of fp16 g2 + bias + log_softmax -> out.
// One warp per node; lane l<20 covers cols 2l, 2l+1.
__global__ void k_gout(const float* __restrict__ b2, float* __restrict__ out, int N) {
    int i = (int)((blockIdx.x * (unsigned)blockDim.x + threadIdx.x) >> 5);
    int l = threadIdx.x & 31;
    if (i >= N) return;
    float v0 = -CUDART_INF_F, v1 = -CUDART_INF_F;
    if (l < 20) {
        int b  = g_rowptr[i];
        int e2 = g_rowptr[i + 1];
        float a0 = 0.f, a1 = 0.f;
        int j = b;
        for (; j + 4 <= e2; j += 4) {
            int s0 = g_csrc[j],     s1 = g_csrc[j + 1];
            int s2 = g_csrc[j + 2], s3 = g_csrc[j + 3];
            float w0 = g_dinv[s0], w1 = g_dinv[s1], w2 = g_dinv[s2], w3 = g_dinv[s3];
            float2 f0 = __half22float2(*(const __half2*)(g_g2h + (size_t)s0 * 20 + l));
            float2 f1 = __half22float2(*(const __half2*)(g_g2h + (size_t)s1 * 20 + l));
            float2 f2 = __half22float2(*(const __half2*)(g_g2h + (size_t)s2 * 20 + l));
            float2 f3 = __half22float2(*(const __half2*)(g_g2h + (size_t)s3 * 20 + l));
            a0 += w0 * f0.x + w1 * f1.x + w2 * f2.x + w3 * f3.x;
            a1 += w0 * f0.y + w1 * f1.y + w2 * f2.y + w3 * f3.y;
        }
        for (; j < e2; j++) {
            int s = g_csrc[j];
            float w = g_dinv[s];
            float2 f = __half22float2(*(const __half2*)(g_g2h + (size_t)s * 20 + l));
            a0 += w * f.x;
            a1 += w * f.y;
        }
        float di = g_dinv[i];
        float d2 = di * di;
        float2 fs = __half22float2(*(const __half2*)(g_g2h + (size_t)i * 20 + l));
        float2 bias = *(const float2*)(b2 + 2 * l);
        v0 = di * a0 + d2 * fs.x + bias.x;
        v1 = di * a1 + d2 * fs.y + bias.y;
    }
    float m = fmaxf(v0, v1);
    #pragma unroll
    for (int o = 16; o; o >>= 1) m = fmaxf(m, __shfl_xor_sync(0xffffffffu, m, o));
    float s = (l < 20) ? (expf(v0 - m) + expf(v1 - m)) : 0.f;
    #pragma unroll
    for (int o = 16; o; o >>= 1) s += __shfl_xor_sync(0xffffffffu, s, o);
    float lse = m + logf(s);
    if (l < 20)
        *(float2*)(out + (size_t)i * NCLS + 2 * l) = make_float2(v0 - lse, v1 - lse);
}

// ---------------------------------------------------------------------------
extern "C" void kernel_launch(void* const* d_in, const int* in_sizes, int n_in,
                              void* d_out, int out_size) {
    const float* x  = (const float*)d_in[0];
    const int*   ei = (const int*)  d_in[1];
    const float* W1 = (const float*)d_in[2];
    const float* b1 = (const float*)d_in[3];
    const float* W2 = (const float*)d_in[4];
    const float* b2 = (const float*)d_in[5];
    float* out = (float*)d_out;

    int N = in_sizes[0] / IN_DIM;
    int E = in_sizes[1] / 2;
    const int* src = ei;
    const int* dst = ei + E;

    static int smem_set = 0;
    const int SMEM_FUSED = (128 * AS_S * 2 + 40 * AS_S) * 4;   // 80,512 B
    if (!smem_set) {
        cudaFuncSetAttribute(k_fused, cudaFuncAttributeMaxDynamicSharedMemorySize,
                             SMEM_FUSED);
        smem_set = 1;
    }

    int NB = (N + SCAN_BLK - 1) / SCAN_BLK;   // 196

    // 7 launches; g_degi is zero on entry (BSS init + scan_a restore)
    k_degw<<<(E + 255) / 256, 256>>>(dst, W1, W2, E);
    k_scan_a<<<NB, 256>>>(N);
    k_scan_c<<<(N + 255) / 256, 256>>>(N, E, NB);
    k_scatter<<<(E + 255) / 256, 256>>>(src, dst, E);

    {
        long threads = (long)N * 32;
        k_gax<<<(int)((threads + 255) / 256), 256>>>(x, N);
    }

    k_fused<<<(N + 127) / 128, 256, SMEM_FUSED>>>(b1, N);

    {
        long threads = (long)N * 32;
        k_gout<<<(int)((threads + 255) / 256), 256>>>(b2, out, N);
    }
}